// round 11
// baseline (speedup 1.0000x reference)
#include <cuda_runtime.h>
#include <cooperative_groups.h>

namespace cg = cooperative_groups;

#define N_VARS 2048
#define P      8
#define BATCH  4096
#define ROW    (N_VARS * P)      // 16384
#define COLS4  (N_VARS / 4)      // 512
#define THREADS 256
#define TOTAL_TILES (BATCH * COLS4)   // 2,097,152 float4 outputs

// 64 KB scratch: diag[lag*N_VARS + i] = weight[i, lag*N_VARS + i]
__device__ float g_diag[P * N_VARS];

__global__ __launch_bounds__(THREADS, 8) void diag_linear_coop(
    const float*  __restrict__ weight,  // (2048, 16384)
    const float4* __restrict__ x,       // (4096, 16384) as float4
    float4*       __restrict__ out)     // (4096, 2048)  as float4
{
    cg::grid_group grid = cg::this_grid();

    const int gtid   = blockIdx.x * THREADS + threadIdx.x;
    const int stride = gridDim.x * THREADS;

    // ---- phase 1: gather the diagonal (first 16384 global threads) ----
    if (gtid < P * N_VARS) {
        int lag = gtid >> 11;                  // / N_VARS
        int i   = gtid & (N_VARS - 1);         // % N_VARS
        g_diag[gtid] = __ldg(&weight[(size_t)i * ROW + lag * N_VARS + i]);
    }

    // ---- phase 2: driver-managed grid barrier (replay-safe, no atomics of ours)
    grid.sync();

    // ---- phase 3: grid-stride streaming body (proven 32-reg / 83%-DRAM loop)
    const float4* diag4 = reinterpret_cast<const float4*>(g_diag);

    for (int tid = gtid; tid < TOTAL_TILES; tid += stride) {
        int b = tid / COLS4;
        int c = tid - b * COLS4;
        const float4* xrow = x + (size_t)b * (ROW / 4);

        float4 acc;
        acc.x = 0.f; acc.y = 0.f; acc.z = 0.f; acc.w = 0.f;

        #pragma unroll
        for (int lag = 0; lag < P; lag++) {
            float4 xv = __ldg(&xrow[lag * COLS4 + c]);
            float4 dv = diag4[lag * COLS4 + c];   // coherent: written this launch
            acc.x = fmaf(xv.x, dv.x, acc.x);
            acc.y = fmaf(xv.y, dv.y, acc.y);
            acc.z = fmaf(xv.z, dv.z, acc.z);
            acc.w = fmaf(xv.w, dv.w, acc.w);
        }
        out[tid] = acc;
    }
}

extern "C" void kernel_launch(void* const* d_in, const int* in_sizes, int n_in,
                              void* d_out, int out_size) {
    const float* x      = (const float*)d_in[0];   // (4096, 16384)
    const float* weight = (const float*)d_in[1];   // (2048, 16384)
    float* out          = (float*)d_out;           // (4096, 2048)

    // Cooperative grids must be fully co-resident: size to SMs x occupancy.
    // Host code runs only at capture time, so these queries are free per replay.
    int device = 0;
    cudaGetDevice(&device);
    int sms = 0;
    cudaDeviceGetAttribute(&sms, cudaDevAttrMultiProcessorCount, device);
    int blocks_per_sm = 0;
    cudaOccupancyMaxActiveBlocksPerMultiprocessor(
        &blocks_per_sm, diag_linear_coop, THREADS, 0);
    if (blocks_per_sm < 1) blocks_per_sm = 1;
    long long grid_ll = (long long)sms * blocks_per_sm;
    if (grid_ll > TOTAL_TILES / THREADS) grid_ll = TOTAL_TILES / THREADS;
    dim3 grid((unsigned int)grid_ll, 1, 1);
    dim3 block(THREADS, 1, 1);

    const float4* x4   = reinterpret_cast<const float4*>(x);
    float4*       out4 = reinterpret_cast<float4*>(out);
    void* args[] = { (void*)&weight, (void*)&x4, (void*)&out4 };

    cudaLaunchCooperativeKernel((void*)diag_linear_coop, grid, block, args, 0, 0);
}

// round 12
// speedup vs baseline: 1.0316x; 1.0316x over previous
#include <cuda_runtime.h>

#define N_VARS 2048
#define P      8
#define BATCH  4096
#define ROW    (N_VARS * P)      // 16384
#define COLS4  (N_VARS / 4)      // 512
#define THREADS 256
#define TOTAL_TILES (BATCH * COLS4)      // 2,097,152 float4 outputs
#define HALF_TILES  (TOTAL_TILES / 2)    // 1,048,576

// 64 KB scratch: diag[lag*N_VARS + i] = weight[i, lag*N_VARS + i]
__device__ float g_diag[P * N_VARS];

__global__ __launch_bounds__(THREADS) void gather_diag_kernel(
    const float* __restrict__ weight)
{
    int idx = blockIdx.x * THREADS + threadIdx.x;  // 0 .. 16383
    int lag = idx >> 11;                           // / N_VARS
    int i   = idx & (N_VARS - 1);                  // % N_VARS
    g_diag[idx] = __ldg(&weight[(size_t)i * ROW + lag * N_VARS + i]);
}

__device__ __forceinline__ float4 tile_compute(
    const float4* __restrict__ x, const float4* __restrict__ diag4, int tid)
{
    int b = tid / COLS4;
    int c = tid - b * COLS4;
    const float4* xrow = x + (size_t)b * (ROW / 4);

    float4 acc;
    acc.x = 0.f; acc.y = 0.f; acc.z = 0.f; acc.w = 0.f;

    #pragma unroll
    for (int lag = 0; lag < P; lag++) {
        float4 xv = __ldg(&xrow[lag * COLS4 + c]);
        float4 dv = __ldg(&diag4[lag * COLS4 + c]);
        acc.x = fmaf(xv.x, dv.x, acc.x);
        acc.y = fmaf(xv.y, dv.y, acc.y);
        acc.z = fmaf(xv.z, dv.z, acc.z);
        acc.w = fmaf(xv.w, dv.w, acc.w);
    }
    return acc;
}

__global__ __launch_bounds__(THREADS) void diag_linear_kernel2(
    const float4* __restrict__ x,    // (4096, 16384) as float4
    float4*       __restrict__ out)  // (4096, 2048)  as float4
{
    int tid = blockIdx.x * THREADS + threadIdx.x;  // 0 .. HALF_TILES-1
    const float4* diag4 = reinterpret_cast<const float4*>(g_diag);

    // tile 1
    out[tid] = tile_compute(x, diag4, tid);
    // tile 2: same column pattern, batch offset BATCH/2 -> identical coalescing
    int tid2 = tid + HALF_TILES;
    out[tid2] = tile_compute(x, diag4, tid2);
}

extern "C" void kernel_launch(void* const* d_in, const int* in_sizes, int n_in,
                              void* d_out, int out_size) {
    const float* x      = (const float*)d_in[0];   // (4096, 16384)
    const float* weight = (const float*)d_in[1];   // (2048, 16384)
    float* out          = (float*)d_out;           // (4096, 2048)

    // 1) gather diagonal: 64 blocks x 256 threads (measured-best shape)
    gather_diag_kernel<<<(P * N_VARS) / THREADS, THREADS>>>(weight);

    // 2) streaming contraction, 2 output tiles per thread (4096 blocks)
    diag_linear_kernel2<<<HALF_TILES / THREADS, THREADS>>>(
        reinterpret_cast<const float4*>(x),
        reinterpret_cast<float4*>(out));
}

// round 13
// speedup vs baseline: 1.0406x; 1.0087x over previous
#include <cuda_runtime.h>

#define N_VARS 2048
#define P      8
#define BATCH  4096
#define ROW    (N_VARS * P)      // 16384
#define COLS4  (N_VARS / 4)      // 512
#define GTHREADS 256             // gather block size (measured best)
#define BTHREADS 512             // body block size (this round's knob)
#define TOTAL_TILES (BATCH * COLS4)   // 2,097,152 float4 outputs

// 64 KB scratch: diag[lag*N_VARS + i] = weight[i, lag*N_VARS + i]
__device__ float g_diag[P * N_VARS];

__global__ __launch_bounds__(GTHREADS) void gather_diag_kernel(
    const float* __restrict__ weight)
{
    int idx = blockIdx.x * GTHREADS + threadIdx.x; // 0 .. 16383
    int lag = idx >> 11;                           // / N_VARS
    int i   = idx & (N_VARS - 1);                  // % N_VARS
    g_diag[idx] = __ldg(&weight[(size_t)i * ROW + lag * N_VARS + i]);
}

__global__ __launch_bounds__(BTHREADS) void diag_linear_kernel(
    const float4* __restrict__ x,    // (4096, 16384) as float4
    float4*       __restrict__ out)  // (4096, 2048)  as float4
{
    int tid = blockIdx.x * BTHREADS + threadIdx.x; // 0 .. TOTAL_TILES-1
    int b = tid / COLS4;
    int c = tid - b * COLS4;

    const float4* xrow  = x + (size_t)b * (ROW / 4);
    const float4* diag4 = reinterpret_cast<const float4*>(g_diag);

    float4 acc;
    acc.x = 0.f; acc.y = 0.f; acc.z = 0.f; acc.w = 0.f;

    #pragma unroll
    for (int lag = 0; lag < P; lag++) {
        float4 xv = __ldg(&xrow[lag * COLS4 + c]);
        float4 dv = __ldg(&diag4[lag * COLS4 + c]);
        acc.x = fmaf(xv.x, dv.x, acc.x);
        acc.y = fmaf(xv.y, dv.y, acc.y);
        acc.z = fmaf(xv.z, dv.z, acc.z);
        acc.w = fmaf(xv.w, dv.w, acc.w);
    }
    out[tid] = acc;
}

extern "C" void kernel_launch(void* const* d_in, const int* in_sizes, int n_in,
                              void* d_out, int out_size) {
    const float* x      = (const float*)d_in[0];   // (4096, 16384)
    const float* weight = (const float*)d_in[1];   // (2048, 16384)
    float* out          = (float*)d_out;           // (4096, 2048)

    // 1) gather diagonal: 64 blocks x 256 threads (measured-best shape)
    gather_diag_kernel<<<(P * N_VARS) / GTHREADS, GTHREADS>>>(weight);

    // 2) streaming contraction: 4096 blocks x 512 threads
    diag_linear_kernel<<<TOTAL_TILES / BTHREADS, BTHREADS>>>(
        reinterpret_cast<const float4*>(x),
        reinterpret_cast<float4*>(out));
}

// round 14
// speedup vs baseline: 1.0471x; 1.0063x over previous
#include <cuda_runtime.h>

#define N_VARS 2048
#define P      8
#define BATCH  4096
#define ROW    (N_VARS * P)      // 16384
#define COLS4  (N_VARS / 4)      // 512
#define THREADS 256

// 64 KB scratch: diag[lag*N_VARS + i] = weight[i, lag*N_VARS + i]
__device__ float g_diag[P * N_VARS];

__global__ __launch_bounds__(THREADS) void gather_diag_kernel(
    const float* __restrict__ weight)
{
    int idx = blockIdx.x * THREADS + threadIdx.x;  // 0 .. 16383
    int lag = idx >> 11;                           // / N_VARS
    int i   = idx & (N_VARS - 1);                  // % N_VARS
    g_diag[idx] = __ldg(&weight[(size_t)i * ROW + lag * N_VARS + i]);
}

__global__ __launch_bounds__(THREADS) void diag_linear_kernel(
    const float4* __restrict__ x,    // (4096, 16384) as float4
    float4*       __restrict__ out)  // (4096, 2048)  as float4
{
    int tid = blockIdx.x * THREADS + threadIdx.x;  // 0 .. BATCH*COLS4-1
    int b = tid / COLS4;
    int c = tid - b * COLS4;

    const float4* xrow  = x + (size_t)b * (ROW / 4);
    const float4* diag4 = reinterpret_cast<const float4*>(g_diag);

    float4 acc;
    acc.x = 0.f; acc.y = 0.f; acc.z = 0.f; acc.w = 0.f;

    #pragma unroll
    for (int lag = 0; lag < P; lag++) {
        float4 xv = __ldg(&xrow[lag * COLS4 + c]);
        float4 dv = __ldg(&diag4[lag * COLS4 + c]);
        acc.x = fmaf(xv.x, dv.x, acc.x);
        acc.y = fmaf(xv.y, dv.y, acc.y);
        acc.z = fmaf(xv.z, dv.z, acc.z);
        acc.w = fmaf(xv.w, dv.w, acc.w);
    }
    out[tid] = acc;
}

extern "C" void kernel_launch(void* const* d_in, const int* in_sizes, int n_in,
                              void* d_out, int out_size) {
    const float* x      = (const float*)d_in[0];   // (4096, 16384)
    const float* weight = (const float*)d_in[1];   // (2048, 16384)
    float* out          = (float*)d_out;           // (4096, 2048)

    // 1) gather diagonal: 64 blocks x 256 threads (measured-best shape)
    gather_diag_kernel<<<(P * N_VARS) / THREADS, THREADS>>>(weight);

    // 2) streaming diagonal contraction (measured-best body: 8192 x 256,
    //    32 regs, ~89% occupancy, ~83% DRAM = 6.57 TB/s, traffic at the
    //    288 MB algebraic floor)
    diag_linear_kernel<<<(BATCH * COLS4) / THREADS, THREADS>>>(
        reinterpret_cast<const float4*>(x),
        reinterpret_cast<float4*>(out));
}

// round 15
// speedup vs baseline: 1.0741x; 1.0258x over previous
#include <cuda_runtime.h>

#define N_VARS 2048
#define P      8
#define BATCH  4096
#define ROW    (N_VARS * P)      // 16384
#define COLS4  (N_VARS / 4)      // 512
#define THREADS 256

// 64 KB scratch: diag[lag*N_VARS + i] = weight[i, lag*N_VARS + i]
__device__ float g_diag[P * N_VARS];

__global__ __launch_bounds__(THREADS) void gather_diag_kernel(
    const float* __restrict__ weight)
{
    int idx = blockIdx.x * THREADS + threadIdx.x;  // 0 .. 16383
    int lag = idx >> 11;                           // / N_VARS
    int i   = idx & (N_VARS - 1);                  // % N_VARS
    g_diag[idx] = __ldg(&weight[(size_t)i * ROW + lag * N_VARS + i]);
}

__global__ __launch_bounds__(THREADS) void diag_linear_kernel(
    const float4* __restrict__ x,    // (4096, 16384) as float4
    float4*       __restrict__ out)  // (4096, 2048)  as float4
{
    int tid = blockIdx.x * THREADS + threadIdx.x;  // 0 .. BATCH*COLS4-1
    int b = tid / COLS4;
    int c = tid - b * COLS4;

    const float4* xrow  = x + (size_t)b * (ROW / 4);
    const float4* diag4 = reinterpret_cast<const float4*>(g_diag);

    float4 acc;
    acc.x = 0.f; acc.y = 0.f; acc.z = 0.f; acc.w = 0.f;

    #pragma unroll
    for (int lag = 0; lag < P; lag++) {
        float4 xv = __ldg(&xrow[lag * COLS4 + c]);
        float4 dv = __ldg(&diag4[lag * COLS4 + c]);
        acc.x = fmaf(xv.x, dv.x, acc.x);
        acc.y = fmaf(xv.y, dv.y, acc.y);
        acc.z = fmaf(xv.z, dv.z, acc.z);
        acc.w = fmaf(xv.w, dv.w, acc.w);
    }
    out[tid] = acc;
}

extern "C" void kernel_launch(void* const* d_in, const int* in_sizes, int n_in,
                              void* d_out, int out_size) {
    const float* x      = (const float*)d_in[0];   // (4096, 16384)
    const float* weight = (const float*)d_in[1];   // (2048, 16384)
    float* out          = (float*)d_out;           // (4096, 2048)

    // 1) gather diagonal: 64 blocks x 256 threads (measured-best shape)
    gather_diag_kernel<<<(P * N_VARS) / THREADS, THREADS>>>(weight);

    // 2) streaming diagonal contraction: 8192 x 256, 32 regs, ~89% occupancy,
    //    DRAM-roofline-bound at ~6.5 TB/s with traffic at the 288 MB floor.
    diag_linear_kernel<<<(BATCH * COLS4) / THREADS, THREADS>>>(
        reinterpret_cast<const float4*>(x),
        reinterpret_cast<float4*>(out));
}